// round 1
// baseline (speedup 1.0000x reference)
#include <cuda_runtime.h>

#define MAX_N 100000
#define HID   16

// Scratch (allocation-free rule: __device__ globals)
__device__ float  g_deg[MAX_N];
__device__ float  g_dinv[MAX_N];
__device__ float  g_px[MAX_N];          // dinv[v] * x[v]
__device__ float  g_s[MAX_N];           // scalar layer-1 aggregate accumulator
__device__ float2 g_gd[MAX_N];          // dinv[v] * g[v, 0:2]
__device__ float2 g_acc[MAX_N];         // layer-2 aggregate accumulator

__global__ void k_init(int n) {
    int i = blockIdx.x * blockDim.x + threadIdx.x;
    if (i < n) {
        g_deg[i] = 1.0f;                // self-loop
        g_s[i]   = 0.0f;
        g_acc[i] = make_float2(0.0f, 0.0f);
    }
}

// degree histogram over dst
__global__ void k_deg(const int* __restrict__ dst, int E) {
    int i = blockIdx.x * blockDim.x + threadIdx.x;
    int base = i * 4;
    if (base + 3 < E) {
        int4 d = *reinterpret_cast<const int4*>(dst + base);
        atomicAdd(&g_deg[d.x], 1.0f);
        atomicAdd(&g_deg[d.y], 1.0f);
        atomicAdd(&g_deg[d.z], 1.0f);
        atomicAdd(&g_deg[d.w], 1.0f);
    } else {
        for (int j = base; j < E; ++j)
            atomicAdd(&g_deg[dst[j]], 1.0f);
    }
}

__global__ void k_dinv_px(const float* __restrict__ x, int n) {
    int i = blockIdx.x * blockDim.x + threadIdx.x;
    if (i < n) {
        float dv = rsqrtf(g_deg[i]);    // deg >= 1 always (self-loop)
        g_dinv[i] = dv;
        g_px[i]   = dv * x[i];
    }
}

// scatter 1: s[dst] += px[src]  (scalar per edge)
__global__ void k_scatter1(const int* __restrict__ src,
                           const int* __restrict__ dst, int E) {
    int i = blockIdx.x * blockDim.x + threadIdx.x;
    int base = i * 4;
    if (base + 3 < E) {
        int4 s4 = *reinterpret_cast<const int4*>(src + base);
        int4 d4 = *reinterpret_cast<const int4*>(dst + base);
        atomicAdd(&g_s[d4.x], __ldg(&g_px[s4.x]));
        atomicAdd(&g_s[d4.y], __ldg(&g_px[s4.y]));
        atomicAdd(&g_s[d4.z], __ldg(&g_px[s4.z]));
        atomicAdd(&g_s[d4.w], __ldg(&g_px[s4.w]));
    } else {
        for (int j = base; j < E; ++j)
            atomicAdd(&g_s[dst[j]], __ldg(&g_px[src[j]]));
    }
}

// per-node dense: finalize s, apply W1/b1 + relu, W2 -> g, pre-scale by dinv
__global__ void k_node(const float* __restrict__ W1, const float* __restrict__ b1,
                       const float* __restrict__ W2, int n) {
    int v = blockIdx.x * blockDim.x + threadIdx.x;
    if (v >= n) return;
    float dv = g_dinv[v];
    float sv = dv * (g_s[v] + g_px[v]);   // + self-loop term dinv*px
    float g0 = 0.0f, g1 = 0.0f;
#pragma unroll
    for (int j = 0; j < HID; ++j) {
        float h = fmaxf(fmaf(sv, __ldg(&W1[j]), __ldg(&b1[j])), 0.0f);
        g0 = fmaf(h, __ldg(&W2[2 * j + 0]), g0);
        g1 = fmaf(h, __ldg(&W2[2 * j + 1]), g1);
    }
    g_gd[v] = make_float2(dv * g0, dv * g1);
}

// scatter 2: acc[dst] += gd[src]  (2 floats per edge)
__global__ void k_scatter2(const int* __restrict__ src,
                           const int* __restrict__ dst, int E) {
    int i = blockIdx.x * blockDim.x + threadIdx.x;
    int base = i * 4;
    if (base + 3 < E) {
        int4 s4 = *reinterpret_cast<const int4*>(src + base);
        int4 d4 = *reinterpret_cast<const int4*>(dst + base);
        float2 a = g_gd[s4.x];
        atomicAdd(&g_acc[d4.x].x, a.x); atomicAdd(&g_acc[d4.x].y, a.y);
        float2 b = g_gd[s4.y];
        atomicAdd(&g_acc[d4.y].x, b.x); atomicAdd(&g_acc[d4.y].y, b.y);
        float2 c = g_gd[s4.z];
        atomicAdd(&g_acc[d4.z].x, c.x); atomicAdd(&g_acc[d4.z].y, c.y);
        float2 d = g_gd[s4.w];
        atomicAdd(&g_acc[d4.w].x, d.x); atomicAdd(&g_acc[d4.w].y, d.y);
    } else {
        for (int j = base; j < E; ++j) {
            float2 a = g_gd[src[j]];
            atomicAdd(&g_acc[dst[j]].x, a.x);
            atomicAdd(&g_acc[dst[j]].y, a.y);
        }
    }
}

__global__ void k_final(const float* __restrict__ b2, float* __restrict__ out, int n) {
    int v = blockIdx.x * blockDim.x + threadIdx.x;
    if (v >= n) return;
    float dv = g_dinv[v];
    float2 acc = g_acc[v];
    float2 gd  = g_gd[v];
    out[2 * v + 0] = dv * (acc.x + gd.x) + __ldg(&b2[0]);
    out[2 * v + 1] = dv * (acc.y + gd.y) + __ldg(&b2[1]);
}

extern "C" void kernel_launch(void* const* d_in, const int* in_sizes, int n_in,
                              void* d_out, int out_size) {
    const float* x  = (const float*)d_in[0];
    const int*   ei = (const int*)d_in[1];       // [2, E]: row0=src, row1=dst
    const float* W1 = (const float*)d_in[2];
    const float* b1 = (const float*)d_in[3];
    const float* W2 = (const float*)d_in[4];
    const float* b2 = (const float*)d_in[5];
    float* out = (float*)d_out;

    int N = in_sizes[0];                 // C_IN = 1
    int E = in_sizes[1] / 2;
    const int* src = ei;
    const int* dst = ei + E;

    const int T = 256;
    int gridN  = (N + T - 1) / T;
    int E4     = (E + 3) / 4;
    int gridE4 = (E4 + T - 1) / T;

    k_init<<<gridN, T>>>(N);
    k_deg<<<gridE4, T>>>(dst, E);
    k_dinv_px<<<gridN, T>>>(x, N);
    k_scatter1<<<gridE4, T>>>(src, dst, E);
    k_node<<<gridN, T>>>(W1, b1, W2, N);
    k_scatter2<<<gridE4, T>>>(src, dst, E);
    k_final<<<gridN, T>>>(b2, out, N);
}

// round 2
// speedup vs baseline: 1.1269x; 1.1269x over previous
#include <cuda_runtime.h>

#define MAX_N 100000
#define HID   16

// Scratch (allocation-free rule: __device__ globals)
__device__ float  g_deg[MAX_N];
__device__ float  g_dinv[MAX_N];
__device__ float  g_px[MAX_N];          // dinv[v] * x[v]
__device__ float  g_s[MAX_N];           // scalar layer-1 aggregate accumulator
__device__ float2 g_gd[MAX_N];          // dinv[v] * g[v, 0:2]
__device__ float2 g_acc[MAX_N];         // layer-2 aggregate accumulator

// one-op 2-float global reduction (sm_90+): halves LTS op count vs 2x atomicAdd
__device__ __forceinline__ void red_add_v2(float2* addr, float a, float b) {
    asm volatile("red.global.relaxed.gpu.add.v2.f32 [%0], {%1, %2};"
                 :: "l"(addr), "f"(a), "f"(b) : "memory");
}

__global__ void k_init(int n) {
    int i = blockIdx.x * blockDim.x + threadIdx.x;
    if (i < n) {
        g_deg[i] = 1.0f;                // self-loop
        g_s[i]   = 0.0f;
        g_acc[i] = make_float2(0.0f, 0.0f);
    }
}

// degree histogram over dst, 8 edges/thread
__global__ void k_deg(const int* __restrict__ dst, int E) {
    int i = blockIdx.x * blockDim.x + threadIdx.x;
    int base = i * 8;
    if (base + 7 < E) {
        int4 d0 = *reinterpret_cast<const int4*>(dst + base);
        int4 d1 = *reinterpret_cast<const int4*>(dst + base + 4);
        atomicAdd(&g_deg[d0.x], 1.0f);
        atomicAdd(&g_deg[d0.y], 1.0f);
        atomicAdd(&g_deg[d0.z], 1.0f);
        atomicAdd(&g_deg[d0.w], 1.0f);
        atomicAdd(&g_deg[d1.x], 1.0f);
        atomicAdd(&g_deg[d1.y], 1.0f);
        atomicAdd(&g_deg[d1.z], 1.0f);
        atomicAdd(&g_deg[d1.w], 1.0f);
    } else {
        for (int j = base; j < E; ++j)
            atomicAdd(&g_deg[dst[j]], 1.0f);
    }
}

__global__ void k_dinv_px(const float* __restrict__ x, int n) {
    int i = blockIdx.x * blockDim.x + threadIdx.x;
    if (i < n) {
        float dv = rsqrtf(g_deg[i]);    // deg >= 1 always (self-loop)
        g_dinv[i] = dv;
        g_px[i]   = dv * x[i];
    }
}

// scatter 1: s[dst] += px[src]  (scalar per edge), 8 edges/thread
__global__ void k_scatter1(const int* __restrict__ src,
                           const int* __restrict__ dst, int E) {
    int i = blockIdx.x * blockDim.x + threadIdx.x;
    int base = i * 8;
    if (base + 7 < E) {
        int4 s0 = *reinterpret_cast<const int4*>(src + base);
        int4 s1 = *reinterpret_cast<const int4*>(src + base + 4);
        int4 d0 = *reinterpret_cast<const int4*>(dst + base);
        int4 d1 = *reinterpret_cast<const int4*>(dst + base + 4);
        // front-batch all 8 gathers for MLP
        float p0 = __ldg(&g_px[s0.x]);
        float p1 = __ldg(&g_px[s0.y]);
        float p2 = __ldg(&g_px[s0.z]);
        float p3 = __ldg(&g_px[s0.w]);
        float p4 = __ldg(&g_px[s1.x]);
        float p5 = __ldg(&g_px[s1.y]);
        float p6 = __ldg(&g_px[s1.z]);
        float p7 = __ldg(&g_px[s1.w]);
        atomicAdd(&g_s[d0.x], p0);
        atomicAdd(&g_s[d0.y], p1);
        atomicAdd(&g_s[d0.z], p2);
        atomicAdd(&g_s[d0.w], p3);
        atomicAdd(&g_s[d1.x], p4);
        atomicAdd(&g_s[d1.y], p5);
        atomicAdd(&g_s[d1.z], p6);
        atomicAdd(&g_s[d1.w], p7);
    } else {
        for (int j = base; j < E; ++j)
            atomicAdd(&g_s[dst[j]], __ldg(&g_px[src[j]]));
    }
}

// per-node dense: finalize s, apply W1/b1 + relu, W2 -> g, pre-scale by dinv
__global__ void k_node(const float* __restrict__ W1, const float* __restrict__ b1,
                       const float* __restrict__ W2, int n) {
    int v = blockIdx.x * blockDim.x + threadIdx.x;
    if (v >= n) return;
    float dv = g_dinv[v];
    float sv = dv * (g_s[v] + g_px[v]);   // + self-loop term dinv*px
    float g0 = 0.0f, g1 = 0.0f;
#pragma unroll
    for (int j = 0; j < HID; ++j) {
        float h = fmaxf(fmaf(sv, __ldg(&W1[j]), __ldg(&b1[j])), 0.0f);
        g0 = fmaf(h, __ldg(&W2[2 * j + 0]), g0);
        g1 = fmaf(h, __ldg(&W2[2 * j + 1]), g1);
    }
    g_gd[v] = make_float2(dv * g0, dv * g1);
}

// scatter 2: acc[dst] += gd[src] via ONE red.v2.f32 per edge, 8 edges/thread
__global__ void k_scatter2(const int* __restrict__ src,
                           const int* __restrict__ dst, int E) {
    int i = blockIdx.x * blockDim.x + threadIdx.x;
    int base = i * 8;
    if (base + 7 < E) {
        int4 s0 = *reinterpret_cast<const int4*>(src + base);
        int4 s1 = *reinterpret_cast<const int4*>(src + base + 4);
        int4 d0 = *reinterpret_cast<const int4*>(dst + base);
        int4 d1 = *reinterpret_cast<const int4*>(dst + base + 4);
        float2 a0 = __ldg(&g_gd[s0.x]);
        float2 a1 = __ldg(&g_gd[s0.y]);
        float2 a2 = __ldg(&g_gd[s0.z]);
        float2 a3 = __ldg(&g_gd[s0.w]);
        float2 a4 = __ldg(&g_gd[s1.x]);
        float2 a5 = __ldg(&g_gd[s1.y]);
        float2 a6 = __ldg(&g_gd[s1.z]);
        float2 a7 = __ldg(&g_gd[s1.w]);
        red_add_v2(&g_acc[d0.x], a0.x, a0.y);
        red_add_v2(&g_acc[d0.y], a1.x, a1.y);
        red_add_v2(&g_acc[d0.z], a2.x, a2.y);
        red_add_v2(&g_acc[d0.w], a3.x, a3.y);
        red_add_v2(&g_acc[d1.x], a4.x, a4.y);
        red_add_v2(&g_acc[d1.y], a5.x, a5.y);
        red_add_v2(&g_acc[d1.z], a6.x, a6.y);
        red_add_v2(&g_acc[d1.w], a7.x, a7.y);
    } else {
        for (int j = base; j < E; ++j) {
            float2 a = __ldg(&g_gd[src[j]]);
            red_add_v2(&g_acc[dst[j]], a.x, a.y);
        }
    }
}

__global__ void k_final(const float* __restrict__ b2, float* __restrict__ out, int n) {
    int v = blockIdx.x * blockDim.x + threadIdx.x;
    if (v >= n) return;
    float dv = g_dinv[v];
    float2 acc = g_acc[v];
    float2 gd  = g_gd[v];
    out[2 * v + 0] = dv * (acc.x + gd.x) + __ldg(&b2[0]);
    out[2 * v + 1] = dv * (acc.y + gd.y) + __ldg(&b2[1]);
}

extern "C" void kernel_launch(void* const* d_in, const int* in_sizes, int n_in,
                              void* d_out, int out_size) {
    const float* x  = (const float*)d_in[0];
    const int*   ei = (const int*)d_in[1];       // [2, E]: row0=src, row1=dst
    const float* W1 = (const float*)d_in[2];
    const float* b1 = (const float*)d_in[3];
    const float* W2 = (const float*)d_in[4];
    const float* b2 = (const float*)d_in[5];
    float* out = (float*)d_out;

    int N = in_sizes[0];                 // C_IN = 1
    int E = in_sizes[1] / 2;
    const int* src = ei;
    const int* dst = ei + E;

    const int T = 256;
    int gridN  = (N + T - 1) / T;
    int E8     = (E + 7) / 8;
    int gridE8 = (E8 + T - 1) / T;

    k_init<<<gridN, T>>>(N);
    k_deg<<<gridE8, T>>>(dst, E);
    k_dinv_px<<<gridN, T>>>(x, N);
    k_scatter1<<<gridE8, T>>>(src, dst, E);
    k_node<<<gridN, T>>>(W1, b1, W2, N);
    k_scatter2<<<gridE8, T>>>(src, dst, E);
    k_final<<<gridN, T>>>(b2, out, N);
}

// round 4
// speedup vs baseline: 1.2454x; 1.1051x over previous
#include <cuda_runtime.h>
#include <cuda_fp16.h>

#define MAX_N 100000
#define HID   16

// Scratch (allocation-free rule: __device__ globals)
__device__ float   g_deg[MAX_N];
__device__ float   g_dinv[MAX_N];
__device__ __half  g_px[MAX_N];          // fp16: dinv[v]*x[v]  (200KB -> L1-resident)
__device__ float   g_s[MAX_N];           // scalar layer-1 aggregate accumulator
__device__ __half2 g_gd[MAX_N];          // fp16x2: dinv[v]*g[v,0:2] (400KB)
__device__ float2  g_acc[MAX_N];         // layer-2 aggregate accumulator (f32)

// one-op 2-float global reduction (sm_90+)
__device__ __forceinline__ void red_add_v2(float2* addr, float a, float b) {
    asm volatile("red.global.relaxed.gpu.add.v2.f32 [%0], {%1, %2};"
                 :: "l"(addr), "f"(a), "f"(b) : "memory");
}

// streaming (evict-first) int4 load for edge indices: keep L1 for gathers
__device__ __forceinline__ int4 ldcs_int4(const int* p) {
    return __ldcs(reinterpret_cast<const int4*>(p));
}

__global__ void k_init(int n) {
    int i = blockIdx.x * blockDim.x + threadIdx.x;
    if (i < n) g_deg[i] = 0.0f;          // self-loop folded into rsqrt(deg+1)
}

// degree histogram over dst, 4 edges/thread
__global__ void k_deg(const int* __restrict__ dst, int E) {
    int i = blockIdx.x * blockDim.x + threadIdx.x;
    int base = i * 4;
    if (base + 3 < E) {
        int4 d = ldcs_int4(dst + base);
        atomicAdd(&g_deg[d.x], 1.0f);
        atomicAdd(&g_deg[d.y], 1.0f);
        atomicAdd(&g_deg[d.z], 1.0f);
        atomicAdd(&g_deg[d.w], 1.0f);
    } else {
        for (int j = base; j < E; ++j)
            atomicAdd(&g_deg[dst[j]], 1.0f);
    }
}

__global__ void k_dinv_px(const float* __restrict__ x, int n) {
    int i = blockIdx.x * blockDim.x + threadIdx.x;
    if (i < n) {
        float dv = rsqrtf(g_deg[i] + 1.0f);   // +1 = self-loop
        g_dinv[i] = dv;
        g_px[i]   = __float2half_rn(dv * x[i]);
        g_s[i]    = 0.0f;                      // zero accumulator for scatter1
    }
}

// scatter 1: s[dst] += px[src]  (scalar per edge), 4 edges/thread
__global__ void k_scatter1(const int* __restrict__ src,
                           const int* __restrict__ dst, int E) {
    int i = blockIdx.x * blockDim.x + threadIdx.x;
    int base = i * 4;
    if (base + 3 < E) {
        int4 s4 = ldcs_int4(src + base);
        int4 d4 = ldcs_int4(dst + base);
        float p0 = __half2float(__ldg(&g_px[s4.x]));
        float p1 = __half2float(__ldg(&g_px[s4.y]));
        float p2 = __half2float(__ldg(&g_px[s4.z]));
        float p3 = __half2float(__ldg(&g_px[s4.w]));
        atomicAdd(&g_s[d4.x], p0);
        atomicAdd(&g_s[d4.y], p1);
        atomicAdd(&g_s[d4.z], p2);
        atomicAdd(&g_s[d4.w], p3);
    } else {
        for (int j = base; j < E; ++j)
            atomicAdd(&g_s[dst[j]], __half2float(__ldg(&g_px[src[j]])));
    }
}

// per-node dense: finalize s, W1/b1 + relu, W2 -> g, pre-scale by dinv; zero acc
__global__ void k_node(const float* __restrict__ W1, const float* __restrict__ b1,
                       const float* __restrict__ W2, int n) {
    int v = blockIdx.x * blockDim.x + threadIdx.x;
    if (v >= n) return;
    float dv = g_dinv[v];
    float sv = dv * (g_s[v] + __half2float(g_px[v]));  // + self-loop term
    float g0 = 0.0f, g1 = 0.0f;
#pragma unroll
    for (int j = 0; j < HID; ++j) {
        float h = fmaxf(fmaf(sv, __ldg(&W1[j]), __ldg(&b1[j])), 0.0f);
        g0 = fmaf(h, __ldg(&W2[2 * j + 0]), g0);
        g1 = fmaf(h, __ldg(&W2[2 * j + 1]), g1);
    }
    g_gd[v]  = __floats2half2_rn(dv * g0, dv * g1);
    g_acc[v] = make_float2(0.0f, 0.0f);                // zero for scatter2
}

// scatter 2: acc[dst] += gd[src] via ONE red.v2.f32 per edge, 4 edges/thread
__global__ void k_scatter2(const int* __restrict__ src,
                           const int* __restrict__ dst, int E) {
    int i = blockIdx.x * blockDim.x + threadIdx.x;
    int base = i * 4;
    if (base + 3 < E) {
        int4 s4 = ldcs_int4(src + base);
        int4 d4 = ldcs_int4(dst + base);
        float2 a0 = __half22float2(__ldg(&g_gd[s4.x]));
        float2 a1 = __half22float2(__ldg(&g_gd[s4.y]));
        float2 a2 = __half22float2(__ldg(&g_gd[s4.z]));
        float2 a3 = __half22float2(__ldg(&g_gd[s4.w]));
        red_add_v2(&g_acc[d4.x], a0.x, a0.y);
        red_add_v2(&g_acc[d4.y], a1.x, a1.y);
        red_add_v2(&g_acc[d4.z], a2.x, a2.y);
        red_add_v2(&g_acc[d4.w], a3.x, a3.y);
    } else {
        for (int j = base; j < E; ++j) {
            float2 a = __half22float2(__ldg(&g_gd[src[j]]));
            red_add_v2(&g_acc[dst[j]], a.x, a.y);
        }
    }
}

__global__ void k_final(const float* __restrict__ b2, float* __restrict__ out, int n) {
    int v = blockIdx.x * blockDim.x + threadIdx.x;
    if (v >= n) return;
    float dv = g_dinv[v];
    float2 acc = g_acc[v];
    float2 gd  = __half22float2(g_gd[v]);
    out[2 * v + 0] = dv * (acc.x + gd.x) + __ldg(&b2[0]);
    out[2 * v + 1] = dv * (acc.y + gd.y) + __ldg(&b2[1]);
}

extern "C" void kernel_launch(void* const* d_in, const int* in_sizes, int n_in,
                              void* d_out, int out_size) {
    const float* x  = (const float*)d_in[0];
    const int*   ei = (const int*)d_in[1];       // [2, E]: row0=src, row1=dst
    const float* W1 = (const float*)d_in[2];
    const float* b1 = (const float*)d_in[3];
    const float* W2 = (const float*)d_in[4];
    const float* b2 = (const float*)d_in[5];
    float* out = (float*)d_out;

    int N = in_sizes[0];                 // C_IN = 1
    int E = in_sizes[1] / 2;
    const int* src = ei;
    const int* dst = ei + E;

    const int T = 256;
    int gridN  = (N + T - 1) / T;
    int E4     = (E + 3) / 4;
    int gridE4 = (E4 + T - 1) / T;

    k_init<<<gridN, T>>>(N);
    k_deg<<<gridE4, T>>>(dst, E);
    k_dinv_px<<<gridN, T>>>(x, N);
    k_scatter1<<<gridE4, T>>>(src, dst, E);
    k_node<<<gridN, T>>>(W1, b1, W2, N);
    k_scatter2<<<gridE4, T>>>(src, dst, E);
    k_final<<<gridN, T>>>(b2, out, N);
}